// round 6
// baseline (speedup 1.0000x reference)
#include <cuda_runtime.h>
#include <cstdint>

typedef unsigned long long ull;

#define C_CH   256
#define NB     32
#define HH     56
#define WW     56
#define HW     3136
#define TOTAL  (NB*C_CH*HW)
#define PP     60                 // padded pitch (floats)
#define PR     58                 // padded rows
#define PSZ    (PP*PR)            // 3480 floats per padded channel-image
#define PTOT   (NB*C_CH*PSZ)
#define NTHR   196                // 14x14 threads, 4x4 px each
#define EPS    1e-5f
#define INVCNT (1.0f/(float)(NB*HW))
#define CONV_SMEM (PSZ*4 + 4*C_CH*9*8)   // 13920 + 73728 = 87648 bytes

// ---- scratch ----
__device__ float g_xp [PTOT];    // padded x
__device__ float g_h1 [PTOT];    // padded raw conv1 out (interior valid only)
__device__ float g_h1b[PTOT];    // padded relu(bn1(h1)) incl zero halo
__device__ float g_h2 [TOTAL];   // unpadded conv2 out
__device__ float g_ps [C_CH*NB];
__device__ float g_ps2[C_CH*NB];
__device__ float g_sc1[C_CH], g_sh1[C_CH];
__device__ float g_sc2[C_CH], g_sh2[C_CH];
__device__ int   g_skip1[C_CH];
__device__ int   g_list1[C_CH], g_list2[C_CH];
__device__ int   g_cnt[2];

// ---- f32x2 helpers (Blackwell packed fp32; ptxas never emits from C++) ----
__device__ __forceinline__ void ffma2(ull& d, ull a, ull b) {
    asm("fma.rn.f32x2 %0, %1, %2, %0;" : "+l"(d) : "l"(a), "l"(b));
}
__device__ __forceinline__ ull pk2(float a, float b) {
    ull d; asm("mov.b64 %0, {%1, %2};" : "=l"(d) : "f"(a), "f"(b)); return d;
}
__device__ __forceinline__ float2 upk(ull d) {
    float x, y; asm("mov.b64 {%0, %1}, %2;" : "=f"(x), "=f"(y) : "l"(d));
    return make_float2(x, y);
}

// ============================================================
// compact both masks into active-channel lists (1 block, 512 thr)
// ============================================================
__global__ void compact_kernel(const float* __restrict__ m1, const float* __restrict__ m2,
                               int* __restrict__ l1, int* __restrict__ l2, int* __restrict__ cnt)
{
    int t = threadIdx.x;
    int h = t >> 8, c = t & 255;
    const float* m = h ? m2 : m1;
    int* l = h ? l2 : l1;
    int a = (m[c] != 0.f);
    unsigned b = __ballot_sync(0xffffffffu, a);
    int lane = t & 31, w = t >> 5;
    __shared__ int wc[16];
    if (lane == 0) wc[w] = __popc(b);
    __syncthreads();
    int w0 = h * 8, base = 0;
    for (int i = w0; i < w; ++i) base += wc[i];
    int pre = __popc(b & ((1u << lane) - 1));
    if (a) l[base + pre] = c;
    if (c == 0) { int s = 0; for (int i = w0; i < w0 + 8; ++i) s += wc[i]; cnt[h] = s; }
}

// ============================================================
// x -> padded layout (zero halo)
// ============================================================
__global__ void pad_x_kernel(const float* __restrict__ x, float* __restrict__ xp)
{
    const int c = blockIdx.x, n = blockIdx.y, tid = threadIdx.x;
    const float* src = x + ((size_t)n * C_CH + c) * HW;
    float4* dst = (float4*)(xp + ((size_t)n * C_CH + c) * PSZ);
    for (int j = tid; j < PSZ / 4; j += 256) {
        int row = j / 15, c4 = (j - row * 15) * 4;
        int y = row - 1;
        float4 o;
        float* po = (float*)&o;
        #pragma unroll
        for (int k = 0; k < 4; ++k) {
            int col = c4 + k, xx = col - 1;
            po[k] = ((unsigned)y < (unsigned)HH && (unsigned)xx < (unsigned)WW)
                    ? src[y * WW + xx] : 0.f;
        }
        dst[j] = o;
    }
}

// ============================================================
// h1(pad raw) -> h1b(pad) = relu(bn1(h1)); zero halo; masked channels constant
// ============================================================
__global__ void bnrelu_pad_kernel(const float* __restrict__ h1, float* __restrict__ h1b,
                                  const float* __restrict__ sc, const float* __restrict__ sh,
                                  const float* __restrict__ mask)
{
    const int c = blockIdx.x, n = blockIdx.y, tid = threadIdx.x;
    const size_t base = ((size_t)n * C_CH + c) * PSZ;
    float4* dst = (float4*)(h1b + base);
    const float s = sc[c], t = sh[c];
    if (mask[c] == 0.f) {
        const float cv = fmaxf(t, 0.f);
        for (int j = tid; j < PSZ / 4; j += 256) {
            int row = j / 15, c4 = (j - row * 15) * 4;
            bool ri = (row >= 1 && row <= HH);
            float4 o;
            float* po = (float*)&o;
            #pragma unroll
            for (int k = 0; k < 4; ++k) {
                int col = c4 + k;
                po[k] = (ri && col >= 1 && col <= WW) ? cv : 0.f;
            }
            dst[j] = o;
        }
        return;
    }
    const float4* srcp = (const float4*)(h1 + base);
    for (int j = tid; j < PSZ / 4; j += 256) {
        int row = j / 15, c4 = (j - row * 15) * 4;
        bool ri = (row >= 1 && row <= HH);
        float4 v = srcp[j];
        const float* pv = (const float*)&v;
        float4 o;
        float* po = (float*)&o;
        #pragma unroll
        for (int k = 0; k < 4; ++k) {
            int col = c4 + k;
            po[k] = (ri && col >= 1 && col <= WW)
                    ? fmaxf(fmaf(pv[k], s, t), 0.f) : 0.f;
        }
        dst[j] = o;
    }
}

// ============================================================
// Direct 3x3 conv via packed FFMA2. One block = (n, quad of active out
// channels). Padded input, pure float4 tile staging, weights duplicated
// to f32x2 pairs in smem. BN partial sums fused into the epilogue.
// ============================================================
template<bool SKIP, bool PADOUT>
__global__ __launch_bounds__(NTHR, 2)
void conv_kernel(const float* __restrict__ in, const float* __restrict__ wts,
                 const float* __restrict__ mask,
                 const int* __restrict__ list, const int* __restrict__ cnt, int cntIdx,
                 const int* __restrict__ skip,
                 float* __restrict__ out,
                 float* __restrict__ ps, float* __restrict__ ps2)
{
    extern __shared__ char smem[];
    float* s_in = (float*)smem;                       // 3480 floats
    ull*   s_w2 = (ull*)(smem + PSZ * 4);             // 4*2304 pairs

    const int n = blockIdx.x;
    const int qb = blockIdx.y * 4;
    const int count = cnt[cntIdx];
    if (qb >= count) return;
    const int tid = threadIdx.x;

    int cidx[4]; bool act[4]; float mv[4];
    #pragma unroll
    for (int j = 0; j < 4; ++j) {
        int idx = qb + j;
        act[j] = idx < count;
        cidx[j] = list[act[j] ? idx : (count - 1)];
        mv[j] = mask[cidx[j]];
    }

    // duplicate weights into f32x2 pairs in smem
    #pragma unroll
    for (int j = 0; j < 4; ++j) {
        const float* wsrc = wts + (size_t)cidx[j] * (C_CH * 9);
        for (int i = tid; i < C_CH * 9; i += NTHR) {
            float w = wsrc[i];
            s_w2[j * (C_CH * 9) + i] = pk2(w, w);
        }
    }

    const int tx = tid % 14, ty = tid / 14;
    const int x0 = tx * 4, y0 = ty * 4;

    ull acc[4][4][2];
    #pragma unroll
    for (int j = 0; j < 4; ++j)
        #pragma unroll
        for (int r = 0; r < 4; ++r) { acc[j][r][0] = 0ull; acc[j][r][1] = 0ull; }

    for (int ci = 0; ci < C_CH; ++ci) {
        if (SKIP && skip[ci]) continue;      // uniform across block
        __syncthreads();
        const float4* src = (const float4*)(in + ((size_t)n * C_CH + ci) * PSZ);
        float4* d4 = (float4*)s_in;
        for (int t = tid; t < PSZ / 4; t += NTHR) d4[t] = src[t];
        __syncthreads();

        #pragma unroll
        for (int r = 0; r < 6; ++r) {
            const float* vp = s_in + (y0 + r) * PP + x0;
            float v0 = vp[0], v1 = vp[1], v2 = vp[2], v3 = vp[3], v4 = vp[4], v5 = vp[5];
            ull p01 = pk2(v0, v1), p12 = pk2(v1, v2), p23 = pk2(v2, v3);
            ull p34 = pk2(v3, v4), p45 = pk2(v4, v5);
            #pragma unroll
            for (int kh = 0; kh < 3; ++kh) {
                const int hr = r - kh;
                if (hr < 0 || hr > 3) continue;
                #pragma unroll
                for (int j = 0; j < 4; ++j) {
                    const ull* wj = s_w2 + j * (C_CH * 9) + ci * 9 + kh * 3;
                    ull wa = wj[0], wb = wj[1], wc = wj[2];
                    ffma2(acc[j][hr][0], wa, p01);
                    ffma2(acc[j][hr][1], wa, p23);
                    ffma2(acc[j][hr][0], wb, p12);
                    ffma2(acc[j][hr][1], wb, p34);
                    ffma2(acc[j][hr][0], wc, p23);
                    ffma2(acc[j][hr][1], wc, p45);
                }
            }
        }
    }

    __syncthreads();   // tile smem now reused for BN reduction

    float s[4], s2[4];
    #pragma unroll
    for (int j = 0; j < 4; ++j) {
        s[j] = 0.f; s2[j] = 0.f;
        const float mm = mv[j];
        float* op;
        int opitch;
        if (PADOUT) {
            op = out + ((size_t)n * C_CH + cidx[j]) * PSZ + (y0 + 1) * PP + (x0 + 1);
            opitch = PP;
        } else {
            op = out + ((size_t)n * C_CH + cidx[j]) * HW + y0 * WW + x0;
            opitch = WW;
        }
        #pragma unroll
        for (int hr = 0; hr < 4; ++hr)
            #pragma unroll
            for (int p = 0; p < 2; ++p) {
                float2 f = upk(acc[j][hr][p]);
                float a0 = f.x * mm, a1 = f.y * mm;
                if (act[j]) { op[hr * opitch + 2 * p] = a0; op[hr * opitch + 2 * p + 1] = a1; }
                s[j]  += a0 + a1;
                s2[j] += a0 * a0 + a1 * a1;
            }
    }

    // fused BN partial: deterministic fixed-order block reduce
    #pragma unroll
    for (int j = 0; j < 4; ++j) {
        s_in[j * NTHR + tid] = s[j];
        s_in[(4 + j) * NTHR + tid] = s2[j];
    }
    __syncthreads();
    if (tid < 8) {
        float t = 0.f;
        const float* rp = s_in + tid * NTHR;
        for (int i = 0; i < NTHR; ++i) t += rp[i];
        int j = tid & 3;
        if (act[j]) {
            if (tid < 4) ps[cidx[j] * NB + n] = t;
            else         ps2[cidx[j] * NB + n] = t;
        }
    }
}

// ============================================================
__global__ void bn_finalize_kernel(const float* __restrict__ ps, const float* __restrict__ ps2,
                                   const float* __restrict__ gamma, const float* __restrict__ beta,
                                   const float* __restrict__ mask,
                                   float* __restrict__ sc, float* __restrict__ sh,
                                   int* __restrict__ skip)
{
    const int c = threadIdx.x;
    float s = 0.f, s2 = 0.f;
    if (mask[c] != 0.f) {
        #pragma unroll 8
        for (int nn = 0; nn < NB; ++nn) { s += ps[c * NB + nn]; s2 += ps2[c * NB + nn]; }
    }
    const float mean = s * INVCNT;
    float var = fmaf(-mean, mean, s2 * INVCNT);
    var = fmaxf(var, 0.f);
    const float t = var + EPS;
    float inv = rsqrtf(t);
    inv = inv * (1.5f - 0.5f * t * inv * inv);
    const float scv = gamma[c] * inv;
    const float shv = fmaf(-mean, scv, beta[c]);
    sc[c] = scv; sh[c] = shv;
    if (skip) skip[c] = (mask[c] == 0.f && shv <= 0.f) ? 1 : 0;
}

// ============================================================
// out = relu(bn2(h2) + x); masked2 channels never wrote h2 -> treat as 0
// ============================================================
__global__ void epilogue_kernel(const float* __restrict__ h2, const float* __restrict__ x,
                                const float* __restrict__ sc, const float* __restrict__ sh,
                                const float* __restrict__ mask2,
                                float* __restrict__ out, int total4)
{
    int i = blockIdx.x * blockDim.x + threadIdx.x;
    if (i >= total4) return;
    const int c = (i / (HW / 4)) & (C_CH - 1);
    const float s = sc[c], t = sh[c];
    float4 a;
    if (mask2[c] != 0.f) a = reinterpret_cast<const float4*>(h2)[i];
    else { a.x = a.y = a.z = a.w = 0.f; }
    float4 b = reinterpret_cast<const float4*>(x)[i];
    float4 o;
    o.x = fmaxf(fmaf(a.x, s, t) + b.x, 0.f);
    o.y = fmaxf(fmaf(a.y, s, t) + b.y, 0.f);
    o.z = fmaxf(fmaf(a.z, s, t) + b.z, 0.f);
    o.w = fmaxf(fmaf(a.w, s, t) + b.w, 0.f);
    reinterpret_cast<float4*>(out)[i] = o;
}

// ============================================================
extern "C" void kernel_launch(void* const* d_in, const int* in_sizes, int n_in,
                              void* d_out, int out_size)
{
    const float* x      = (const float*)d_in[0];
    const float* W1     = (const float*)d_in[1];
    const float* W2     = (const float*)d_in[2];
    const float* gamma1 = (const float*)d_in[3];
    const float* beta1  = (const float*)d_in[4];
    const float* gamma2 = (const float*)d_in[5];
    const float* beta2  = (const float*)d_in[6];
    const float* mask1  = (const float*)d_in[7];
    const float* mask2  = (const float*)d_in[8];
    float* out = (float*)d_out;

    float *xp, *h1, *h1b, *h2, *ps, *ps2, *sc1, *sh1, *sc2, *sh2;
    int *skip1, *list1, *list2, *cnt;
    cudaGetSymbolAddress((void**)&xp,   g_xp);
    cudaGetSymbolAddress((void**)&h1,   g_h1);
    cudaGetSymbolAddress((void**)&h1b,  g_h1b);
    cudaGetSymbolAddress((void**)&h2,   g_h2);
    cudaGetSymbolAddress((void**)&ps,   g_ps);
    cudaGetSymbolAddress((void**)&ps2,  g_ps2);
    cudaGetSymbolAddress((void**)&sc1,  g_sc1);
    cudaGetSymbolAddress((void**)&sh1,  g_sh1);
    cudaGetSymbolAddress((void**)&sc2,  g_sc2);
    cudaGetSymbolAddress((void**)&sh2,  g_sh2);
    cudaGetSymbolAddress((void**)&skip1, g_skip1);
    cudaGetSymbolAddress((void**)&list1, g_list1);
    cudaGetSymbolAddress((void**)&list2, g_list2);
    cudaGetSymbolAddress((void**)&cnt,   g_cnt);

    cudaFuncSetAttribute(conv_kernel<false, true>,
                         cudaFuncAttributeMaxDynamicSharedMemorySize, CONV_SMEM);
    cudaFuncSetAttribute(conv_kernel<true, false>,
                         cudaFuncAttributeMaxDynamicSharedMemorySize, CONV_SMEM);

    // 0: active-channel lists
    compact_kernel<<<1, 512>>>(mask1, mask2, list1, list2, cnt);

    // 1: pad x
    pad_x_kernel<<<dim3(C_CH, NB), 256>>>(x, xp);

    // 2: conv1 (padded in -> padded out) + fused BN1 partials
    conv_kernel<false, true><<<dim3(NB, C_CH / 4), NTHR, CONV_SMEM>>>(
        xp, W1, mask1, list1, cnt, 0, nullptr, h1, ps, ps2);

    // 3: BN1 finalize (+ conv2 input-channel skip flags)
    bn_finalize_kernel<<<1, C_CH>>>(ps, ps2, gamma1, beta1, mask1, sc1, sh1, skip1);

    // 4: h1b = relu(bn1(h1)) padded
    bnrelu_pad_kernel<<<dim3(C_CH, NB), 256>>>(h1, h1b, sc1, sh1, mask1);

    // 5: conv2 (skips dead input channels) + fused BN2 partials
    conv_kernel<true, false><<<dim3(NB, C_CH / 4), NTHR, CONV_SMEM>>>(
        h1b, W2, mask2, list2, cnt, 1, skip1, h2, ps, ps2);

    // 6: BN2 finalize
    bn_finalize_kernel<<<1, C_CH>>>(ps, ps2, gamma2, beta2, mask2, sc2, sh2, nullptr);

    // 7: out = relu(bn2(h2) + x)
    const int total4 = TOTAL / 4;
    epilogue_kernel<<<(total4 + 255) / 256, 256>>>(h2, x, sc2, sh2, mask2, out, total4);
}

// round 11
// speedup vs baseline: 7.0374x; 7.0374x over previous
#include <cuda_runtime.h>
#include <cstdint>

#define C_CH 256
#define NB 32
#define PD 58
#define HH 56
#define WW 56
#define HW 3136
#define EPS 1e-5f
#define INVCNT (1.0f/(float)(NB*HW))
#define NT4 1792               // 448 tiles * 4 warp-cols
#define BBYTES 32256           // 224 rows * 36 floats * 4B
#define STAGE  48640           // BBYTES + 16384 (A)
#define SMEMT  (3*STAGE)       // 145920

// ---- scratch (device globals; BSS zero-init, written deterministically) ----
__device__ float g_xt [(size_t)NB*PD*PD*C_CH];   // padded NHWC x, tf32 (halo stays 0)
__device__ float g_h1b[(size_t)NB*PD*PD*C_CH];   // compacted-channel padded NHWC h1 -> bn1relu in place
__device__ float g_h2 [(size_t)NB*HW*C_CH];      // conv2 out NHWC (real co)
__device__ float g_A1[72*2*4096];                // frag-permuted weights conv1
__device__ float g_A2[72*2*4096];
__device__ float g_ps [C_CH*NT4], g_ps2[C_CH*NT4];
__device__ float g_sc1[C_CH], g_sh1[C_CH], g_sc2[C_CH], g_sh2[C_CH];
__device__ int   g_list1[C_CH], g_list2[C_CH], g_cnt[2];

// ---- helpers ----
__device__ __forceinline__ uint32_t smem_u32(const void* p){
    uint32_t a;
    asm("{ .reg .u64 t; cvta.to.shared.u64 t, %1; cvt.u32.u64 %0, t; }" : "=r"(a) : "l"(p));
    return a;
}
__device__ __forceinline__ float tf32r(float x){
    uint32_t u; asm("cvt.rna.tf32.f32 %0, %1;" : "=r"(u) : "f"(x));
    return __uint_as_float(u);
}
#define CPA16(dst, src) \
    asm volatile("cp.async.cg.shared.global [%0], [%1], 16;" :: "r"(dst), "l"(src))
#define MMA8(ac, av, b0, b1) \
    asm volatile("mma.sync.aligned.m16n8k8.row.col.f32.tf32.tf32.f32 " \
        "{%0,%1,%2,%3},{%4,%5,%6,%7},{%8,%9},{%0,%1,%2,%3};" \
        : "+f"((ac)[0]), "+f"((ac)[1]), "+f"((ac)[2]), "+f"((ac)[3]) \
        : "r"(__float_as_uint((av).x)), "r"(__float_as_uint((av).y)), \
          "r"(__float_as_uint((av).z)), "r"(__float_as_uint((av).w)), \
          "r"(__float_as_uint(b0)), "r"(__float_as_uint(b1)))

// ============================================================
// TF32 mma.sync implicit-GEMM conv.
// CTA: (ytile, n, mtile). D[128 co][224 px = 4 rows x 56].
// K = 9 taps x KC ci-blocks of 32.  3-stage cp.async pipeline.
// Warps: 2(M) x 4(N): warp = 64 co x 56 px. acc[4 m16][7 n8][4].
// A in smem is fragment-ordered (pre-permuted in gmem): 1 LDS.128/frag.
// B rows padded to 36 floats -> conflict-free b-frag LDS.
// ============================================================
template<bool C2>
__global__ __launch_bounds__(256, 1)
void conv_mma()
{
    extern __shared__ char smem[];
    const int tid = threadIdx.x, lane = tid & 31, wid = tid >> 5;
    const int wr = wid >> 2, wc = wid & 3;
    const int yt = blockIdx.x, n = blockIdx.y, mz = blockIdx.z;
    const int y0 = yt * 4;
    const int cntM = g_cnt[C2 ? 1 : 0];
    const int mbase = mz * 128;
    if (mbase >= cntM) return;      // uniform across block

    int inKP, KC;
    if (C2) { const int c1 = g_cnt[0]; inKP = (c1 + 31) & ~31; KC = inKP >> 5; }
    else    { inKP = 256; KC = 8; }
    const int NCH = 9 * KC;
    const float* in = C2 ? g_h1b : g_xt;
    const float* Ap = C2 ? g_A2  : g_A1;
    const int*  lst = C2 ? g_list2 : g_list1;

    // precomputed staging offsets
    const int jj = tid & 7;
    int prm[7], dstB[7];
    #pragma unroll
    for (int it = 0; it < 7; ++it) {
        const int p = (tid >> 3) + it * 32;
        prm[it]  = ((y0 + p / 56) * PD + (p % 56)) * inKP;
        dstB[it] = p * 144 + jj * 16;
    }
    const uint32_t sb = smem_u32(smem);
    const float* bimg = in + (size_t)n * PD * PD * inKP + jj * 4;

    float acc[4][7][4];
    #pragma unroll
    for (int i = 0; i < 4; ++i)
        #pragma unroll
        for (int nn = 0; nn < 7; ++nn)
            #pragma unroll
            for (int k = 0; k < 4; ++k) acc[i][nn][k] = 0.f;

    // ---- stage loader ----
    auto stage_load = [&](int q, int s) {
        int tap, cb;
        if (C2) { tap = q / KC; cb = q - tap * KC; } else { tap = q >> 3; cb = q & 7; }
        const int dyxm = ((tap / 3) * PD + (tap % 3)) * inKP + cb * 32;
        const uint32_t ds = sb + s * STAGE;
        #pragma unroll
        for (int it = 0; it < 7; ++it)
            CPA16(ds + dstB[it], bimg + prm[it] + dyxm);
        const float* as = Ap + ((size_t)q * 2 + mz) * 4096 + tid * 4;
        const uint32_t da = ds + BBYTES + tid * 16;
        #pragma unroll
        for (int it = 0; it < 4; ++it)
            CPA16(da + it * 4096, as + it * 1024);
        asm volatile("cp.async.commit_group;");
    };

    stage_load(0, 0);
    if (NCH > 1) stage_load(1, 1);

    const int browbase = (wc * 56 + (lane >> 2)) * 36 + (lane & 3);

    for (int q = 0; q < NCH; ++q) {
        // On the last chunk the just-committed group IS the one we read:
        // must drain fully (wait_group 0), not leave 1 pending.
        if (q + 1 < NCH) asm volatile("cp.async.wait_group 1;");
        else             asm volatile("cp.async.wait_group 0;");
        __syncthreads();
        const int s = q % 3;
        const float* sB = (const float*)(smem + s * STAGE);
        const float* sA = (const float*)(smem + s * STAGE + BBYTES);
        #pragma unroll
        for (int st = 0; st < 4; ++st) {
            float4 a[4];
            #pragma unroll
            for (int i = 0; i < 4; ++i)
                a[i] = *(const float4*)(sA + ((wr * 4 + i) * 4 + st) * 128 + lane * 4);
            #pragma unroll
            for (int nn = 0; nn < 7; ++nn) {
                const float b0 = sB[browbase + nn * 288 + st * 8];
                const float b1 = sB[browbase + nn * 288 + st * 8 + 4];
                #pragma unroll
                for (int i = 0; i < 4; ++i) MMA8(acc[i][nn], a[i], b0, b1);
            }
        }
        __syncthreads();
        if (q + 2 < NCH) stage_load(q + 2, (q + 2) % 3);
    }

    // ---- epilogue: store + BN partials (quad shfl, deterministic) ----
    const int tile4 = (n * 14 + yt) * 4 + wc;
    float* obase;
    int ostr;
    if (C2) { obase = g_h2 + ((size_t)(n * HH + y0 + wc) * WW) * C_CH; ostr = C_CH; }
    else {
        const int kp = (cntM + 31) & ~31;
        obase = g_h1b + ((size_t)(n * PD + y0 + wc + 1) * PD + 1) * kp; ostr = kp;
    }
    #pragma unroll
    for (int i = 0; i < 4; ++i)
        #pragma unroll
        for (int half = 0; half < 2; ++half) {
            const int co_pos = mbase + wr * 64 + i * 16 + (lane >> 2) + half * 8;
            const bool ok = co_pos < cntM;
            const int creal = ok ? lst[co_pos] : 0;
            float* op = obase + (C2 ? creal : co_pos);
            float s = 0.f, s2 = 0.f;
            #pragma unroll
            for (int nn = 0; nn < 7; ++nn) {
                const float v0 = acc[i][nn][half * 2];
                const float v1 = acc[i][nn][half * 2 + 1];
                const int x = nn * 8 + (lane & 3) * 2;
                if (ok) { op[(size_t)x * ostr] = v0; op[(size_t)(x + 1) * ostr] = v1; }
                s += v0 + v1;
                s2 += v0 * v0 + v1 * v1;
            }
            s  += __shfl_xor_sync(0xffffffffu, s, 1);
            s  += __shfl_xor_sync(0xffffffffu, s, 2);
            s2 += __shfl_xor_sync(0xffffffffu, s2, 1);
            s2 += __shfl_xor_sync(0xffffffffu, s2, 2);
            if (ok && (lane & 3) == 0) {
                g_ps [creal * NT4 + tile4] = s;
                g_ps2[creal * NT4 + tile4] = s2;
            }
        }
}

// ============================================================
// compact both masks into active-channel lists
// ============================================================
__global__ void compact_kernel(const float* __restrict__ m1, const float* __restrict__ m2)
{
    const int t = threadIdx.x, h = t >> 8, c = t & 255;
    const float* m = h ? m2 : m1;
    int* l = h ? g_list2 : g_list1;
    const int a = (m[c] != 0.f);
    const unsigned b = __ballot_sync(0xffffffffu, a);
    const int lane = t & 31, w = t >> 5;
    __shared__ int wcnt[16];
    if (lane == 0) wcnt[w] = __popc(b);
    __syncthreads();
    const int w0 = h * 8;
    int base = 0;
    for (int i = w0; i < w; ++i) base += wcnt[i];
    if (a) l[base + __popc(b & ((1u << lane) - 1))] = c;
    if (c == 0) { int s = 0; for (int i = w0; i < w0 + 8; ++i) s += wcnt[i]; g_cnt[h] = s; }
}

// ============================================================
// weight prep -> fragment-permuted A buffers (masks folded in)
// ============================================================
__global__ void wprep(const float* __restrict__ W1, const float* __restrict__ W2,
                      const float* __restrict__ m1, const float* __restrict__ m2)
{
    const int q = blockIdx.x, mt = blockIdx.y, which = blockIdx.z;
    const int tid = threadIdx.x, lane = tid & 31, grp = tid >> 5;
    const int cnt0 = g_cnt[0];
    int tap, cb, cm;
    const float *W, *mk;
    const int* lst;
    float* A;
    if (which) {
        const int kc = ((cnt0 + 31) & ~31) >> 5;
        if (q >= 9 * kc) return;
        tap = q / kc; cb = q - tap * kc;
        cm = g_cnt[1]; W = W2; mk = m2; lst = g_list2; A = g_A2;
    } else {
        tap = q >> 3; cb = q & 7;
        cm = cnt0; W = W1; mk = m1; lst = g_list1; A = g_A1;
    }
    const int wr = grp >> 2, i = grp & 3;
    float* dst = A + ((size_t)q * 2 + mt) * 4096;
    #pragma unroll
    for (int st = 0; st < 4; ++st)
        #pragma unroll
        for (int j = 0; j < 4; ++j) {
            const int r16 = (lane >> 2) + ((j & 1) ? 8 : 0);
            const int col = (lane & 3) + ((j & 2) ? 4 : 0);
            const int co_pos = mt * 128 + wr * 64 + i * 16 + r16;
            const int kidx = cb * 32 + st * 8 + col;
            float v = 0.f;
            if (co_pos < cm) {
                const int co = lst[co_pos];
                const int ci = which ? ((kidx < cnt0) ? g_list1[kidx] : -1) : kidx;
                if (ci >= 0) v = tf32r(W[((size_t)co * 256 + ci) * 9 + tap] * mk[co]);
            }
            dst[((grp * 4 + st) * 32 + lane) * 4 + j] = v;
        }
}

// ============================================================
// x: NCHW -> padded NHWC (tf32), halo stays BSS-zero
// ============================================================
__global__ void xform_x(const float* __restrict__ x)
{
    __shared__ float s[32][57];
    const int cb = blockIdx.x, y = blockIdx.y, n = blockIdx.z, tid = threadIdx.x;
    #pragma unroll
    for (int k = 0; k < 7; ++k) {
        const int idx = tid + k * 256, c = idx / 56, xx = idx - c * 56;
        s[c][xx] = x[(((size_t)n * C_CH + cb * 32 + c) * HH + y) * WW + xx];
    }
    __syncthreads();
    #pragma unroll
    for (int k = 0; k < 7; ++k) {
        const int idx = tid + k * 256, xx = idx >> 5, c = idx & 31;
        g_xt[(((size_t)n * PD + y + 1) * PD + (xx + 1)) * C_CH + cb * 32 + c] = tf32r(s[c][xx]);
    }
}

// ============================================================
// BN finalize (block per channel; masked channels -> zero stats)
// ============================================================
__global__ void bn_fin(const float* __restrict__ gamma, const float* __restrict__ beta,
                       const float* __restrict__ mask,
                       float* __restrict__ sc, float* __restrict__ sh)
{
    const int c = blockIdx.x, tid = threadIdx.x;
    __shared__ float r1[256], r2[256];
    float s = 0.f, s2 = 0.f;
    if (mask[c] != 0.f)
        for (int i = tid; i < NT4; i += 256) { s += g_ps[c * NT4 + i]; s2 += g_ps2[c * NT4 + i]; }
    r1[tid] = s; r2[tid] = s2;
    __syncthreads();
    for (int o = 128; o > 0; o >>= 1) {
        if (tid < o) { r1[tid] += r1[tid + o]; r2[tid] += r2[tid + o]; }
        __syncthreads();
    }
    if (tid == 0) {
        const float mean = r1[0] * INVCNT;
        float var = fmaxf(fmaf(-mean, mean, r2[0] * INVCNT), 0.f);
        const float t = var + EPS;
        float inv = rsqrtf(t);
        inv = inv * (1.5f - 0.5f * t * inv * inv);
        const float scv = gamma[c] * inv;
        sc[c] = scv;
        sh[c] = fmaf(-mean, scv, beta[c]);
    }
}

// ============================================================
// h1b in place: relu(bn1(v)) tf32, compacted channels only
// ============================================================
__global__ void bnrelu()
{
    const int y = blockIdx.x, n = blockIdx.y, c = threadIdx.x;
    const int cnt0 = g_cnt[0];
    if (c >= cnt0) return;
    const int kp = (cnt0 + 31) & ~31;
    const int cr = g_list1[c];
    const float s = g_sc1[cr], t = g_sh1[cr];
    float* row = g_h1b + ((size_t)(n * PD + y + 1) * PD + 1) * kp + c;
    #pragma unroll 4
    for (int xx = 0; xx < WW; ++xx) {
        const float v = row[(size_t)xx * kp];
        row[(size_t)xx * kp] = tf32r(fmaxf(fmaf(v, s, t), 0.f));
    }
}

// ============================================================
// out(NCHW) = relu(bn2(h2 NHWC) + x)
// ============================================================
__global__ void epi_t(const float* __restrict__ xin, const float* __restrict__ mask2,
                      float* __restrict__ out)
{
    __shared__ float s[32][57];
    __shared__ float scs[32], shs[32];
    const int cb = blockIdx.x, y = blockIdx.y, n = blockIdx.z, tid = threadIdx.x;
    if (tid < 32) { scs[tid] = g_sc2[cb * 32 + tid]; shs[tid] = g_sh2[cb * 32 + tid]; }
    __syncthreads();
    #pragma unroll
    for (int k = 0; k < 7; ++k) {
        const int idx = tid + k * 256, xx = idx >> 5, c = idx & 31;
        const float v = (mask2[cb * 32 + c] != 0.f)
            ? g_h2[(((size_t)n * HH + y) * WW + xx) * C_CH + cb * 32 + c] : 0.f;
        s[c][xx] = fmaf(v, scs[c], shs[c]);
    }
    __syncthreads();
    #pragma unroll
    for (int k = 0; k < 7; ++k) {
        const int idx = tid + k * 256, c = idx / 56, xx = idx - c * 56;
        const size_t o = (((size_t)n * C_CH + cb * 32 + c) * HH + y) * WW + xx;
        out[o] = fmaxf(s[c][xx] + xin[o], 0.f);
    }
}

// ============================================================
extern "C" void kernel_launch(void* const* d_in, const int* in_sizes, int n_in,
                              void* d_out, int out_size)
{
    const float* x      = (const float*)d_in[0];
    const float* W1     = (const float*)d_in[1];
    const float* W2     = (const float*)d_in[2];
    const float* gamma1 = (const float*)d_in[3];
    const float* beta1  = (const float*)d_in[4];
    const float* gamma2 = (const float*)d_in[5];
    const float* beta2  = (const float*)d_in[6];
    const float* mask1  = (const float*)d_in[7];
    const float* mask2  = (const float*)d_in[8];
    float* out = (float*)d_out;

    void *p_sc1, *p_sh1, *p_sc2, *p_sh2;
    cudaGetSymbolAddress(&p_sc1, g_sc1);
    cudaGetSymbolAddress(&p_sh1, g_sh1);
    cudaGetSymbolAddress(&p_sc2, g_sc2);
    cudaGetSymbolAddress(&p_sh2, g_sh2);

    cudaFuncSetAttribute(conv_mma<false>, cudaFuncAttributeMaxDynamicSharedMemorySize, SMEMT);
    cudaFuncSetAttribute(conv_mma<true>,  cudaFuncAttributeMaxDynamicSharedMemorySize, SMEMT);

    compact_kernel<<<1, 512>>>(mask1, mask2);
    wprep<<<dim3(72, 2, 2), 256>>>(W1, W2, mask1, mask2);
    xform_x<<<dim3(8, 56, 32), 256>>>(x);

    conv_mma<false><<<dim3(14, NB, 2), 256, SMEMT>>>();
    bn_fin<<<256, 256>>>(gamma1, beta1, mask1, (float*)p_sc1, (float*)p_sh1);
    bnrelu<<<dim3(56, NB), 256>>>();

    conv_mma<true><<<dim3(14, NB, 2), 256, SMEMT>>>();
    bn_fin<<<256, 256>>>(gamma2, beta2, mask2, (float*)p_sc2, (float*)p_sh2);

    epi_t<<<dim3(8, 56, 32), 256>>>(x, mask2, out);
}